// round 4
// baseline (speedup 1.0000x reference)
#include <cuda_runtime.h>
#include <cuda_bf16.h>
#include <math.h>
#include <stdint.h>

#define BATCH 4096
#define SQ    64
#define DM    256
#define NH    8
#define HDIM  32
#define FFD   1024
#define NL    6
#define MTOK  (BATCH*SQ)   /* 262144 */

// ---------------- scratch (no allocations allowed) ----------------
__device__ float g_x[MTOK*DM];            // fp32 residual stream
__device__ float g_qkv[MTOK*3*DM];        // fp32 qkv for attention
__device__ float g_y[MTOK*DM];            // fp32 sublayer output
__device__ float g_pe[SQ*DM];
__device__ float g_vh[BATCH*DM];
__device__ float g_ch[BATCH*DM];

// split bf16 activation buffers
__device__ __nv_bfloat16 g_xh[MTOK*DM],  g_xl[MTOK*DM];
__device__ __nv_bfloat16 g_oh[MTOK*DM],  g_ol[MTOK*DM];
__device__ __nv_bfloat16 g_fh[MTOK*FFD], g_fl[MTOK*FFD];
__device__ __nv_bfloat16 g_h1h[BATCH*1024], g_h1l[BATCH*1024];
__device__ __nv_bfloat16 g_ph[BATCH*DM], g_pl[BATCH*DM];

// split bf16 weight pool
#define OFF_QKV 0UL
#define OFF_OUT 1179648UL
#define OFF_FF1 1572864UL
#define OFF_FF2 3145728UL
#define OFF_VW1 4718592UL
#define OFF_CW1 4784128UL
#define OFF_PW1 4849664UL
#define OFF_PW2 21626880UL
#define WPOOL   25821184UL
__device__ __nv_bfloat16 g_wh[WPOOL], g_wl[WPOOL];

// ---------------- helpers ----------------
__device__ __forceinline__ void splitf(float v, __nv_bfloat16& h, __nv_bfloat16& l) {
    h = __float2bfloat16(v);
    l = __float2bfloat16(v - __bfloat162float(h));
}

__device__ __forceinline__ void mma_bf16(float* c, const uint32_t* a, const uint32_t* b) {
    asm volatile(
        "mma.sync.aligned.m16n8k16.row.col.f32.bf16.bf16.f32 "
        "{%0,%1,%2,%3}, {%4,%5,%6,%7}, {%8,%9}, {%0,%1,%2,%3};\n"
        : "+f"(c[0]), "+f"(c[1]), "+f"(c[2]), "+f"(c[3])
        : "r"(a[0]), "r"(a[1]), "r"(a[2]), "r"(a[3]), "r"(b[0]), "r"(b[1]));
}

__device__ __forceinline__ void ldsm4(uint32_t& r0, uint32_t& r1, uint32_t& r2, uint32_t& r3,
                                      uint32_t a) {
    asm volatile("ldmatrix.sync.aligned.m8n8.x4.shared.b16 {%0,%1,%2,%3}, [%4];"
                 : "=r"(r0), "=r"(r1), "=r"(r2), "=r"(r3) : "r"(a));
}

__device__ __forceinline__ void cpa16(uint32_t s, const void* g) {
    asm volatile("cp.async.cg.shared.global [%0], [%1], 16;" :: "r"(s), "l"(g));
}

// ---------------- weight/activation split kernel ----------------
__global__ void split_kernel(const float* __restrict__ in,
                             __nv_bfloat16* __restrict__ hi,
                             __nv_bfloat16* __restrict__ lo, int n4) {
    int i = blockIdx.x * 256 + threadIdx.x;
    if (i >= n4) return;
    float4 v = ((const float4*)in)[i];
    __nv_bfloat16 h[4], l[4];
    splitf(v.x, h[0], l[0]); splitf(v.y, h[1], l[1]);
    splitf(v.z, h[2], l[2]); splitf(v.w, h[3], l[3]);
    *(uint2*)&hi[(size_t)i * 4] = *(uint2*)h;
    *(uint2*)&lo[(size_t)i * 4] = *(uint2*)l;
}

// ---------------- PE precompute ----------------
__global__ void pe_kernel(float* __restrict__ pe) {
    int s = blockIdx.x, d = threadIdx.x;
    int row = s >> 3, col = s & 7;
    int m = d >> 1;
    float div = powf(10000.0f, (2.0f * (float)m) / 256.0f);
    float v = (d & 1) ? cosf((float)col / div) : sinf((float)row / div);
    pe[s * DM + d] = v;
}

// ---------------- tokens + embedding + PE (+split) ----------------
__global__ void embed_kernel(const float* __restrict__ board,
                             const float* __restrict__ emb,
                             const float* __restrict__ pe,
                             float* __restrict__ x,
                             __nv_bfloat16* __restrict__ xh,
                             __nv_bfloat16* __restrict__ xl) {
    int tokidx = blockIdx.x;          // b*64 + s
    int b = tokidx >> 6, s = tokidx & 63;
    __shared__ float ch[14];
    __shared__ int tok;
    int d = threadIdx.x;              // 256 threads
    if (d < 14) ch[d] = board[(size_t)b * 896 + (size_t)d * 64 + s];
    __syncthreads();
    if (d == 0) {
        float mx = ch[0]; int idx = 0;
        #pragma unroll
        for (int c = 1; c < 14; c++) { if (ch[c] > mx) { mx = ch[c]; idx = c; } }
        tok = (mx > 0.0f) ? (idx + 1) : 0;
    }
    __syncthreads();
    float v = emb[tok * DM + d] + pe[s * DM + d];
    size_t o = (size_t)tokidx * DM + d;
    x[o] = v;
    __nv_bfloat16 h, l; splitf(v, h, l);
    xh[o] = h; xl[o] = l;
}

// ---------------- split-bf16 tensor GEMM ----------------
// C[M,N] = A[M,K] @ W[N,K]^T + bias (+relu / +split output)
// BM=BN=128, BK=16, 256 threads = 8 warps, warp tile 64x32 via m16n8k16.
// 3-term emulation: Ah*Wh + Ah*Wl + Al*Wh, fp32 accumulate.
// 2-stage cp.async pipeline, ldmatrix.x4 fragments.
#define SK 24                       /* padded row stride in bf16 */
#define ARRB (128*SK*2)             /* bytes per array: 6144 */
#define STGB (4*ARRB)               /* bytes per stage: 24576 */

#define GMODE_F32        0
#define GMODE_F32_RELU   1
#define GMODE_SPLIT_RELU 2

__global__ __launch_bounds__(256, 2) void gemm_split(
    const __nv_bfloat16* __restrict__ Ahg, const __nv_bfloat16* __restrict__ Alg,
    const __nv_bfloat16* __restrict__ Whg, const __nv_bfloat16* __restrict__ Wlg,
    const float* __restrict__ bias,
    float* __restrict__ C,
    __nv_bfloat16* __restrict__ Chi, __nv_bfloat16* __restrict__ Clo,
    int M, int N, int K, int mode)
{
    __shared__ __nv_bfloat16 sm[2 * 4 * 128 * SK];   // 49152 B
    uint32_t smu = (uint32_t)__cvta_generic_to_shared(sm);

    int tid = threadIdx.x;
    int wid = tid >> 5, lane = tid & 31;
    int grp = lane >> 2, tig = lane & 3;
    int wm = (wid >> 2) * 64;
    int wn = (wid & 3) * 32;
    int bm = blockIdx.y * 128, bn = blockIdx.x * 128;

    float acc[4][4][4];
    #pragma unroll
    for (int i = 0; i < 4; i++)
        #pragma unroll
        for (int j = 0; j < 4; j++)
            #pragma unroll
            for (int r = 0; r < 4; r++) acc[i][j][r] = 0.0f;

    // per-thread load slot: one 16B granule per array
    const int lrow = tid >> 1;          // 0..127
    const int lcs  = (tid & 1) * 8;     // col seg (bf16 elems)
    const uint32_t sto = (uint32_t)((lrow * SK + lcs) * 2);
    const size_t ga = (size_t)(bm + lrow) * K + lcs;
    const size_t gw = (size_t)(bn + lrow) * K + lcs;

    auto issue = [&](int s, int k0) {
        uint32_t sb = smu + (uint32_t)s * STGB + sto;
        cpa16(sb + 0 * ARRB, Ahg + ga + k0);
        cpa16(sb + 1 * ARRB, Alg + ga + k0);
        cpa16(sb + 2 * ARRB, Whg + gw + k0);
        cpa16(sb + 3 * ARRB, Wlg + gw + k0);
    };

    const int r15 = lane & 15;
    const int c8  = (lane >> 4) * 8;
    const int nk = K >> 4;

    issue(0, 0);
    asm volatile("cp.async.commit_group;" ::: "memory");

    for (int it = 0; it < nk; it++) {
        int s = it & 1;
        if (it + 1 < nk) {
            issue(s ^ 1, (it + 1) << 4);
            asm volatile("cp.async.commit_group;" ::: "memory");
            asm volatile("cp.async.wait_group 1;" ::: "memory");
        } else {
            asm volatile("cp.async.wait_group 0;" ::: "memory");
        }
        __syncthreads();

        uint32_t ab  = smu + (uint32_t)s * STGB;
        uint32_t alb = ab + 1 * ARRB;
        uint32_t wb  = ab + 2 * ARRB;
        uint32_t wlb = ab + 3 * ARRB;

        uint32_t ah[4][4], al[4][4], bh[4][2], bl[4][2];
        #pragma unroll
        for (int mf = 0; mf < 4; mf++) {
            uint32_t off = (uint32_t)(((wm + mf * 16 + r15) * SK + c8) * 2);
            ldsm4(ah[mf][0], ah[mf][1], ah[mf][2], ah[mf][3], ab + off);
            ldsm4(al[mf][0], al[mf][1], al[mf][2], al[mf][3], alb + off);
        }
        #pragma unroll
        for (int hf = 0; hf < 2; hf++) {
            uint32_t off = (uint32_t)(((wn + hf * 16 + r15) * SK + c8) * 2);
            uint32_t r0, r1, r2, r3;
            ldsm4(r0, r1, r2, r3, wb + off);
            bh[hf * 2][0] = r0; bh[hf * 2][1] = r2;
            bh[hf * 2 + 1][0] = r1; bh[hf * 2 + 1][1] = r3;
            ldsm4(r0, r1, r2, r3, wlb + off);
            bl[hf * 2][0] = r0; bl[hf * 2][1] = r2;
            bl[hf * 2 + 1][0] = r1; bl[hf * 2 + 1][1] = r3;
        }
        #pragma unroll
        for (int mf = 0; mf < 4; mf++)
            #pragma unroll
            for (int nf = 0; nf < 4; nf++) {
                mma_bf16(acc[mf][nf], ah[mf], bh[nf]);   // hi*hi
                mma_bf16(acc[mf][nf], ah[mf], bl[nf]);   // hi*lo
                mma_bf16(acc[mf][nf], al[mf], bh[nf]);   // lo*hi
            }
        __syncthreads();
    }

    // epilogue: lane owns cols tig*2, tig*2+1, rows grp / grp+8 per fragment
    #pragma unroll
    for (int mf = 0; mf < 4; mf++) {
        int m = bm + wm + mf * 16 + grp;
        #pragma unroll
        for (int nf = 0; nf < 4; nf++) {
            int n = bn + wn + nf * 8 + tig * 2;
            float b0 = bias ? bias[n] : 0.0f;
            float b1 = bias ? bias[n + 1] : 0.0f;
            float v0 = acc[mf][nf][0] + b0;
            float v1 = acc[mf][nf][1] + b1;
            float v2 = acc[mf][nf][2] + b0;
            float v3 = acc[mf][nf][3] + b1;
            if (mode != GMODE_F32) {
                v0 = fmaxf(v0, 0.0f); v1 = fmaxf(v1, 0.0f);
                v2 = fmaxf(v2, 0.0f); v3 = fmaxf(v3, 0.0f);
            }
            if (mode == GMODE_SPLIT_RELU) {
                __nv_bfloat16 h0, l0, h1, l1;
                __nv_bfloat162 hv, lv;
                splitf(v0, h0, l0); splitf(v1, h1, l1);
                hv.x = h0; hv.y = h1; lv.x = l0; lv.y = l1;
                *(__nv_bfloat162*)&Chi[(size_t)m * N + n] = hv;
                *(__nv_bfloat162*)&Clo[(size_t)m * N + n] = lv;
                splitf(v2, h0, l0); splitf(v3, h1, l1);
                hv.x = h0; hv.y = h1; lv.x = l0; lv.y = l1;
                *(__nv_bfloat162*)&Chi[(size_t)(m + 8) * N + n] = hv;
                *(__nv_bfloat162*)&Clo[(size_t)(m + 8) * N + n] = lv;
            } else {
                *(float2*)&C[(size_t)m * N + n]       = make_float2(v0, v1);
                *(float2*)&C[(size_t)(m + 8) * N + n] = make_float2(v2, v3);
            }
        }
    }
}

// ---------------- attention: one CTA per (b, h), register-blocked fp32 ----------------
__global__ __launch_bounds__(256) void attn_kernel(const float* __restrict__ qkv,
                                                   __nv_bfloat16* __restrict__ oh,
                                                   __nv_bfloat16* __restrict__ ol) {
    int bh = blockIdx.x;
    int b = bh >> 3, h = bh & 7;
    __shared__ float qt[32][68];   // [d][i] transposed
    __shared__ float kt[32][68];   // [d][j] transposed
    __shared__ float vsm[64][36];  // [j][d]
    __shared__ float sc[64][68];   // [i][j]
    int tid = threadIdx.x;

    #pragma unroll
    for (int t = tid; t < 512; t += 256) {
        int row = t >> 3, dc = (t & 7) << 2;
        size_t base = ((size_t)b * 64 + row) * 768 + h * 32 + dc;
        float4 qv = *(const float4*)&qkv[base];
        float4 kv = *(const float4*)&qkv[base + 256];
        float4 vv = *(const float4*)&qkv[base + 512];
        qt[dc][row] = qv.x; qt[dc + 1][row] = qv.y; qt[dc + 2][row] = qv.z; qt[dc + 3][row] = qv.w;
        kt[dc][row] = kv.x; kt[dc + 1][row] = kv.y; kt[dc + 2][row] = kv.z; kt[dc + 3][row] = kv.w;
        *(float4*)&vsm[row][dc] = vv;
    }
    __syncthreads();

    {
        int i0 = (tid >> 4) << 2;
        int j0 = (tid & 15) << 2;
        float a[4][4];
        #pragma unroll
        for (int ii = 0; ii < 4; ii++)
            #pragma unroll
            for (int jj = 0; jj < 4; jj++) a[ii][jj] = 0.0f;
        #pragma unroll
        for (int d = 0; d < 32; d++) {
            float4 q4 = *(const float4*)&qt[d][i0];
            float4 k4 = *(const float4*)&kt[d][j0];
            float qv[4] = {q4.x, q4.y, q4.z, q4.w};
            float kv[4] = {k4.x, k4.y, k4.z, k4.w};
            #pragma unroll
            for (int ii = 0; ii < 4; ii++)
                #pragma unroll
                for (int jj = 0; jj < 4; jj++)
                    a[ii][jj] = fmaf(qv[ii], kv[jj], a[ii][jj]);
        }
        const float scale = 0.17677669529663687f;
        #pragma unroll
        for (int ii = 0; ii < 4; ii++) {
            *(float4*)&sc[i0 + ii][j0] = make_float4(a[ii][0] * scale, a[ii][1] * scale,
                                                     a[ii][2] * scale, a[ii][3] * scale);
        }
    }
    __syncthreads();

    {
        int r = tid >> 2;
        int c0 = (tid & 3) << 4;
        float e[16];
        float mx = -1e30f;
        #pragma unroll
        for (int c = 0; c < 16; c++) { e[c] = sc[r][c0 + c]; mx = fmaxf(mx, e[c]); }
        mx = fmaxf(mx, __shfl_xor_sync(0xffffffffu, mx, 1));
        mx = fmaxf(mx, __shfl_xor_sync(0xffffffffu, mx, 2));
        float sum = 0.0f;
        #pragma unroll
        for (int c = 0; c < 16; c++) { e[c] = __expf(e[c] - mx); sum += e[c]; }
        sum += __shfl_xor_sync(0xffffffffu, sum, 1);
        sum += __shfl_xor_sync(0xffffffffu, sum, 2);
        float inv = 1.0f / sum;
        #pragma unroll
        for (int c = 0; c < 16; c++) sc[r][c0 + c] = e[c] * inv;
    }
    __syncthreads();

    {
        int i0 = (tid >> 3) << 1;
        int d0 = (tid & 7) << 2;
        float a0[4] = {0, 0, 0, 0}, a1[4] = {0, 0, 0, 0};
        #pragma unroll 8
        for (int j = 0; j < 64; j++) {
            float s0 = sc[i0][j];
            float s1 = sc[i0 + 1][j];
            float4 v4 = *(const float4*)&vsm[j][d0];
            float vv[4] = {v4.x, v4.y, v4.z, v4.w};
            #pragma unroll
            for (int dd = 0; dd < 4; dd++) {
                a0[dd] = fmaf(s0, vv[dd], a0[dd]);
                a1[dd] = fmaf(s1, vv[dd], a1[dd]);
            }
        }
        size_t ob = ((size_t)b * 64 + i0) * DM + h * 32 + d0;
        __nv_bfloat16 hh[4], ll[4];
        #pragma unroll
        for (int dd = 0; dd < 4; dd++) splitf(a0[dd], hh[dd], ll[dd]);
        *(uint2*)&oh[ob] = *(uint2*)hh;
        *(uint2*)&ol[ob] = *(uint2*)ll;
        #pragma unroll
        for (int dd = 0; dd < 4; dd++) splitf(a1[dd], hh[dd], ll[dd]);
        *(uint2*)&oh[ob + DM] = *(uint2*)hh;
        *(uint2*)&ol[ob + DM] = *(uint2*)ll;
    }
}

// ---------------- residual + layernorm (row-wise, +split) ----------------
__global__ __launch_bounds__(256) void add_ln_kernel(float* __restrict__ x,
                                                     const float* __restrict__ y,
                                                     const float* __restrict__ gg,
                                                     const float* __restrict__ bb,
                                                     __nv_bfloat16* __restrict__ xh,
                                                     __nv_bfloat16* __restrict__ xl) {
    size_t base = (size_t)blockIdx.x * 256;
    int d = threadIdx.x;
    float t = x[base + d] + y[base + d];
    __shared__ float red[8];
    __shared__ float stat;
    float s = t;
    #pragma unroll
    for (int off = 16; off; off >>= 1) s += __shfl_xor_sync(0xffffffffu, s, off);
    if ((d & 31) == 0) red[d >> 5] = s;
    __syncthreads();
    if (d == 0) { float m = 0; for (int i = 0; i < 8; i++) m += red[i]; stat = m * (1.0f / 256.0f); }
    __syncthreads();
    float mean = stat;
    float c = t - mean;
    s = c * c;
    #pragma unroll
    for (int off = 16; off; off >>= 1) s += __shfl_xor_sync(0xffffffffu, s, off);
    __syncthreads();
    if ((d & 31) == 0) red[d >> 5] = s;
    __syncthreads();
    if (d == 0) { float v = 0; for (int i = 0; i < 8; i++) v += red[i]; stat = rsqrtf(v * (1.0f / 256.0f) + 1e-5f); }
    __syncthreads();
    float v = c * stat * gg[d] + bb[d];
    x[base + d] = v;
    __nv_bfloat16 h, l; splitf(v, h, l);
    xh[base + d] = h; xl[base + d] = l;
}

// ---------------- mean pooling (+split) ----------------
__global__ void pool_kernel(const float* __restrict__ x,
                            __nv_bfloat16* __restrict__ ph,
                            __nv_bfloat16* __restrict__ pl) {
    int b = blockIdx.x, d = threadIdx.x;
    float s = 0.0f;
    #pragma unroll 8
    for (int i = 0; i < 64; i++) s += x[((size_t)b * 64 + i) * DM + d];
    float v = s * (1.0f / 64.0f);
    __nv_bfloat16 h, l; splitf(v, h, l);
    ph[(size_t)b * DM + d] = h;
    pl[(size_t)b * DM + d] = l;
}

// ---------------- tiny head finals (value / classification) ----------------
__global__ void head_final_kernel(const float* __restrict__ hid,
                                  const float* __restrict__ w,
                                  const float* __restrict__ bias,
                                  float* __restrict__ out, int nout, int do_tanh) {
    int b = blockIdx.x;
    int lane = threadIdx.x;  // 32 threads
    for (int o = 0; o < nout; o++) {
        float s = 0.0f;
        #pragma unroll
        for (int i = lane; i < 256; i += 32) s = fmaf(hid[(size_t)b * 256 + i], w[o * 256 + i], s);
        #pragma unroll
        for (int off = 16; off; off >>= 1) s += __shfl_xor_sync(0xffffffffu, s, off);
        if (lane == 0) {
            float v = s + bias[o];
            out[(size_t)b * nout + o] = do_tanh ? tanhf(v) : v;
        }
    }
}

// ---------------- host side ----------------
struct WPtrs { __nv_bfloat16 *h, *l; };

static inline void gemm(const __nv_bfloat16* Ah, const __nv_bfloat16* Al,
                        const __nv_bfloat16* Wh, const __nv_bfloat16* Wl,
                        const float* bias, float* C,
                        __nv_bfloat16* Chi, __nv_bfloat16* Clo,
                        int M, int N, int K, int mode) {
    dim3 g(N / 128, M / 128), blk(256);
    gemm_split<<<g, blk>>>(Ah, Al, Wh, Wl, bias, C, Chi, Clo, M, N, K, mode);
}

static inline void split(const float* in, __nv_bfloat16* hi, __nv_bfloat16* lo, size_t n) {
    int n4 = (int)(n / 4);
    split_kernel<<<(n4 + 255) / 256, 256>>>(in, hi, lo, n4);
}

extern "C" void kernel_launch(void* const* d_in, const int* in_sizes, int n_in,
                              void* d_out, int out_size) {
    const float* board = (const float*)d_in[0];
    const float* emb   = (const float*)d_in[1];
    const float* qkv_w = (const float*)d_in[2];
    const float* qkv_b = (const float*)d_in[3];
    const float* out_w = (const float*)d_in[4];
    const float* out_b = (const float*)d_in[5];
    const float* ln1_g = (const float*)d_in[6];
    const float* ln1_b = (const float*)d_in[7];
    const float* ln2_g = (const float*)d_in[8];
    const float* ln2_b = (const float*)d_in[9];
    const float* ff1_w = (const float*)d_in[10];
    const float* ff1_b = (const float*)d_in[11];
    const float* ff2_w = (const float*)d_in[12];
    const float* ff2_b = (const float*)d_in[13];
    const float* vw1 = (const float*)d_in[14];
    const float* vb1 = (const float*)d_in[15];
    const float* vw2 = (const float*)d_in[16];
    const float* vb2 = (const float*)d_in[17];
    const float* pw1 = (const float*)d_in[18];
    const float* pb1 = (const float*)d_in[19];
    const float* pw2 = (const float*)d_in[20];
    const float* pb2 = (const float*)d_in[21];
    const float* cw1 = (const float*)d_in[22];
    const float* cb1 = (const float*)d_in[23];
    const float* cw2 = (const float*)d_in[24];
    const float* cb2 = (const float*)d_in[25];

    float* out = (float*)d_out;
    float* out_value  = out;
    float* out_policy = out + BATCH;
    float* out_class  = out + BATCH + (size_t)BATCH * 4096;

    float *px, *pqkv, *py, *ppe, *pvh, *pch;
    cudaGetSymbolAddress((void**)&px,   g_x);
    cudaGetSymbolAddress((void**)&pqkv, g_qkv);
    cudaGetSymbolAddress((void**)&py,   g_y);
    cudaGetSymbolAddress((void**)&ppe,  g_pe);
    cudaGetSymbolAddress((void**)&pvh,  g_vh);
    cudaGetSymbolAddress((void**)&pch,  g_ch);

    __nv_bfloat16 *xh, *xl, *oh, *ol, *fh, *fl, *h1h, *h1l, *ph, *pl, *wh, *wl;
    cudaGetSymbolAddress((void**)&xh,  g_xh);  cudaGetSymbolAddress((void**)&xl,  g_xl);
    cudaGetSymbolAddress((void**)&oh,  g_oh);  cudaGetSymbolAddress((void**)&ol,  g_ol);
    cudaGetSymbolAddress((void**)&fh,  g_fh);  cudaGetSymbolAddress((void**)&fl,  g_fl);
    cudaGetSymbolAddress((void**)&h1h, g_h1h); cudaGetSymbolAddress((void**)&h1l, g_h1l);
    cudaGetSymbolAddress((void**)&ph,  g_ph);  cudaGetSymbolAddress((void**)&pl,  g_pl);
    cudaGetSymbolAddress((void**)&wh,  g_wh);  cudaGetSymbolAddress((void**)&wl,  g_wl);

    // split all weights into the bf16 pool
    split(qkv_w, wh + OFF_QKV, wl + OFF_QKV, 6UL * 768 * 256);
    split(out_w, wh + OFF_OUT, wl + OFF_OUT, 6UL * 256 * 256);
    split(ff1_w, wh + OFF_FF1, wl + OFF_FF1, 6UL * 1024 * 256);
    split(ff2_w, wh + OFF_FF2, wl + OFF_FF2, 6UL * 256 * 1024);
    split(vw1,   wh + OFF_VW1, wl + OFF_VW1, 256UL * 256);
    split(cw1,   wh + OFF_CW1, wl + OFF_CW1, 256UL * 256);
    split(pw1,   wh + OFF_PW1, wl + OFF_PW1, 1024UL * 16384);
    split(pw2,   wh + OFF_PW2, wl + OFF_PW2, 4096UL * 1024);

    pe_kernel<<<SQ, DM>>>(ppe);
    embed_kernel<<<MTOK, DM>>>(board, emb, ppe, px, xh, xl);

    for (int l = 0; l < NL; l++) {
        size_t oq = OFF_QKV + (size_t)l * 768 * 256;
        size_t oo = OFF_OUT + (size_t)l * 256 * 256;
        size_t o1 = OFF_FF1 + (size_t)l * 1024 * 256;
        size_t o2 = OFF_FF2 + (size_t)l * 256 * 1024;

        gemm(xh, xl, wh + oq, wl + oq, qkv_b + (size_t)l * 768, pqkv, 0, 0,
             MTOK, 768, 256, GMODE_F32);
        attn_kernel<<<BATCH * NH, 256>>>(pqkv, oh, ol);
        gemm(oh, ol, wh + oo, wl + oo, out_b + (size_t)l * 256, py, 0, 0,
             MTOK, 256, 256, GMODE_F32);
        add_ln_kernel<<<MTOK, 256>>>(px, py, ln1_g + l * DM, ln1_b + l * DM, xh, xl);
        gemm(xh, xl, wh + o1, wl + o1, ff1_b + (size_t)l * 1024, 0, fh, fl,
             MTOK, 1024, 256, GMODE_SPLIT_RELU);
        gemm(fh, fl, wh + o2, wl + o2, ff2_b + (size_t)l * 256, py, 0, 0,
             MTOK, 256, 1024, GMODE_F32);
        add_ln_kernel<<<MTOK, 256>>>(px, py, ln2_g + l * DM, ln2_b + l * DM, xh, xl);
    }

    // heads
    pool_kernel<<<BATCH, DM>>>(px, ph, pl);

    gemm(ph, pl, wh + OFF_VW1, wl + OFF_VW1, vb1, pvh, 0, 0, BATCH, 256, 256, GMODE_F32_RELU);
    head_final_kernel<<<BATCH, 32>>>(pvh, vw2, vb2, out_value, 1, 1);

    gemm(xh, xl, wh + OFF_PW1, wl + OFF_PW1, pb1, 0, h1h, h1l,
         BATCH, 1024, 16384, GMODE_SPLIT_RELU);   // x viewed as [B, 64*256]
    gemm(h1h, h1l, wh + OFF_PW2, wl + OFF_PW2, pb2, out_policy, 0, 0,
         BATCH, 4096, 1024, GMODE_F32);

    gemm(ph, pl, wh + OFF_CW1, wl + OFF_CW1, cb1, pch, 0, 0, BATCH, 256, 256, GMODE_F32_RELU);
    head_final_kernel<<<BATCH, 32>>>(pch, cw2, cb2, out_class, 3, 0);
}